// round 8
// baseline (speedup 1.0000x reference)
#include <cuda_runtime.h>
#include <math.h>

#define Bn   8
#define Cn   64
#define Nn   4096
#define On   64
#define KNN  20
#define SLOPE 0.2f
#define EPSC  1e-5f

// packed fp32x2 FMA (sm_103a) — only reachable via PTX
#define FMA_F32X2(d, a, b) \
    asm("fma.rn.f32x2 %0, %1, %2, %0;" : "+l"(d) : "l"(a), "l"(b))
#define PACK_F32X2(out, lo, hi) \
    asm("mov.b64 %0, {%1, %2};" : "=l"(out) : "f"(lo), "f"(hi))

// ---------------- device scratch ----------------
__device__ float g_xx[Bn * Nn];
__device__ int   g_idx[Bn * Nn * KNN];
__device__ float g_u[Bn * Nn * On];
__device__ float g_v[Bn * Nn * On];
__device__ float g_sel[Bn * Nn * On];
__device__ float g_sum[On];
__device__ float g_sumsq[On];
__device__ float g_cA[On];
__device__ float g_cB[On];

// ---------------- K1: squared norms ----------------
__global__ void xx_kernel(const float* __restrict__ x) {
    int i = blockIdx.x * 256 + threadIdx.x;
    int b = i >> 12;
    int n = i & (Nn - 1);
    const float* xp = x + b * Cn * Nn + n;
    float s = 0.f;
#pragma unroll
    for (int c = 0; c < Cn; ++c) {
        float v = xp[c * Nn];
        s = fmaf(v, v, s);
    }
    g_xx[i] = s;
}

// ---------------- K2: distance GEMM + top-K (R5 config + float4 loader) ------
// 256 threads = 16 rg x 16 cg; thread computes 4 rows x 8 cols (two LDS.128
// groups colA/colB, conflict-free). 2 CTAs/SM, 128 regs (NO reg-count cap:
// R6 proved forcing 3 CTAs spills vals/acc to local = 3x regression).
#define RT 64
#define MTile 128
#define SKEW 36

#define OFF_XC   0                    // 64*64 f   = 16384 B
#define OFF_XXM  16384                // 128 f     = 512 B
#define OFF_XM   16896                // 64*128 f  = 32768 B
#define OFF_SC   49664                // 256*36 f  = 36864 B
#define OFF_MINV 86528                // 256 f     = 1024 B
#define OFF_MV   0                    // 256*20 f (post-loop reuse)
#define OFF_MI   20480                // 256*20 i (post-loop reuse)
#define SMEM_KNN 87552

__global__ void __launch_bounds__(256, 2) knn_kernel(const float* __restrict__ x) {
    extern __shared__ char smraw[];
    float* s_xc   = (float*)(smraw + OFF_XC);
    float* s_xxm  = (float*)(smraw + OFF_XXM);
    float* s_xm   = (float*)(smraw + OFF_XM);
    float* s_sc   = (float*)(smraw + OFF_SC);
    float* s_minv = (float*)(smraw + OFF_MINV);
    float* s_mv   = (float*)(smraw + OFF_MV);
    int*   s_mi   = (int*)  (smraw + OFF_MI);

    int t  = threadIdx.x;
    int b  = blockIdx.x >> 6;
    int n0 = (blockIdx.x & 63) * RT;
    const float*  xb  = x + b * Cn * Nn;
    const float4* xb4 = (const float4*)xb;        // row stride Nn/4 = 1024

    // center tile [c][row], vectorized: 64*64/4 = 1024 float4, 4 per thread
    {
        float4* s_xc4 = (float4*)s_xc;
#pragma unroll
        for (int i = t; i < Cn * RT / 4; i += 256) {
            int c = i >> 4, r4 = i & 15;          // 16 float4 per row of 64
            s_xc4[c * 16 + r4] = xb4[c * (Nn / 4) + (n0 >> 2) + r4];
        }
    }
    s_minv[t] = -INFINITY;

    int cg = t & 15, rg = t >> 4;
    int row0 = rg * 4;
    int colA = cg * 4;            // cols colA..colA+3
    int colB = 64 + cg * 4;       // cols colB..colB+3
    int qA = cg >> 3;             // quarter of colA (0 or 1)
    int slot = (cg & 7) * 4;

    float vals[KNN];
    int   idxs[KNN];
#pragma unroll
    for (int j = 0; j < KNN; ++j) { vals[j] = -INFINITY; idxs[j] = 0x7fffffff; }

    int sbase = t * SKEW;          // scan-owner base
    int mcol0 = (t & 3) * 32;      // scan-owner column quarter
    int thrb  = t & ~3;            // row's 4 owners

    float4* s_xm4 = (float4*)s_xm;
    const float4* gxx4 = (const float4*)(g_xx + b * Nn);

    for (int m0 = 0; m0 < Nn; m0 += MTile) {
        // candidate tile: 64*128/4 = 2048 float4, 8 per thread (LDG.128/STS.128)
#pragma unroll
        for (int i = t; i < Cn * MTile / 4; i += 256) {
            int c = i >> 5, m4 = i & 31;          // 32 float4 per row of 128
            s_xm4[c * 32 + m4] = xb4[c * (Nn / 4) + (m0 >> 2) + m4];
        }
        if (t < MTile / 4) ((float4*)s_xxm)[t] = gxx4[(m0 >> 2) + t];
        __syncthreads();

        unsigned long long acc2[4][4];
#pragma unroll
        for (int rr = 0; rr < 4; ++rr)
#pragma unroll
            for (int jp = 0; jp < 4; ++jp) acc2[rr][jp] = 0ULL;

#pragma unroll 8
        for (int c = 0; c < Cn; ++c) {
            float4 xr = *(const float4*)(s_xc + c * RT + row0);
            ulonglong2 A0 = *(const ulonglong2*)(s_xm + c * MTile + colA);
            ulonglong2 A1 = *(const ulonglong2*)(s_xm + c * MTile + colB);
            unsigned long long av2[4] = {A0.x, A0.y, A1.x, A1.y};
            unsigned long long rs[4];
            PACK_F32X2(rs[0], xr.x, xr.x);
            PACK_F32X2(rs[1], xr.y, xr.y);
            PACK_F32X2(rs[2], xr.z, xr.z);
            PACK_F32X2(rs[3], xr.w, xr.w);
#pragma unroll
            for (int rr = 0; rr < 4; ++rr)
#pragma unroll
                for (int jp = 0; jp < 4; ++jp)
                    FMA_F32X2(acc2[rr][jp], rs[rr], av2[jp]);
        }

        // stage scores owner-major: owner = row*4 + quarter, slot = col%32
        float4 xxA = *(const float4*)(s_xxm + colA);
        float4 xxB = *(const float4*)(s_xxm + colB);
#pragma unroll
        for (int rr = 0; rr < 4; ++rr) {
            float2 pa0 = *reinterpret_cast<float2*>(&acc2[rr][0]);
            float2 pa1 = *reinterpret_cast<float2*>(&acc2[rr][1]);
            float2 pb0 = *reinterpret_cast<float2*>(&acc2[rr][2]);
            float2 pb1 = *reinterpret_cast<float2*>(&acc2[rr][3]);
            float4 scA = make_float4(fmaf(2.f, pa0.x, -xxA.x),
                                     fmaf(2.f, pa0.y, -xxA.y),
                                     fmaf(2.f, pa1.x, -xxA.z),
                                     fmaf(2.f, pa1.y, -xxA.w));
            float4 scB = make_float4(fmaf(2.f, pb0.x, -xxB.x),
                                     fmaf(2.f, pb0.y, -xxB.y),
                                     fmaf(2.f, pb1.x, -xxB.z),
                                     fmaf(2.f, pb1.y, -xxB.w));
            int owA = (row0 + rr) * 4 + qA;
            *(float4*)(s_sc + owA * SKEW + slot)       = scA;
            *(float4*)(s_sc + (owA + 2) * SKEW + slot) = scB;
        }
        __syncthreads();

        // shared row threshold (benign-stale read)
        float thr = fmaxf(fmaxf(s_minv[thrb], s_minv[thrb + 1]),
                          fmaxf(s_minv[thrb + 2], s_minv[thrb + 3]));

        // prescan: load 32 scores, tile max
        float4 sc4[8];
#pragma unroll
        for (int q = 0; q < 8; ++q) sc4[q] = *(const float4*)(s_sc + sbase + q * 4);
        float tmax = -INFINITY;
#pragma unroll
        for (int q = 0; q < 8; ++q) {
            tmax = fmaxf(tmax, fmaxf(fmaxf(sc4[q].x, sc4[q].y), fmaxf(sc4[q].z, sc4[q].w)));
        }
        float thr_eff = fmaxf(thr, vals[KNN - 1]);

        if (tmax > thr_eff) {
            int mbase = m0 + mcol0;
            const float* scr = (const float*)sc4;
#pragma unroll
            for (int j = 0; j < 32; ++j) {
                float sc = scr[j];
                if (sc > vals[KNN - 1] && sc > thr) {
                    vals[KNN - 1] = sc; idxs[KNN - 1] = mbase + j;
#pragma unroll
                    for (int qq = KNN - 1; qq > 0; --qq) {
                        bool sw = vals[qq] > vals[qq - 1];
                        float tv = sw ? vals[qq - 1] : vals[qq];
                        float tu = sw ? vals[qq]     : vals[qq - 1];
                        int   ti = sw ? idxs[qq - 1] : idxs[qq];
                        int   tj = sw ? idxs[qq]     : idxs[qq - 1];
                        vals[qq] = tv; vals[qq - 1] = tu;
                        idxs[qq] = ti; idxs[qq - 1] = tj;
                    }
                }
            }
            s_minv[t] = vals[KNN - 1];
        }
        __syncthreads();
    }

    // dump per-thread sorted lists
#pragma unroll
    for (int j = 0; j < KNN; ++j) {
        s_mv[t * KNN + j] = vals[j];
        s_mi[t * KNN + j] = idxs[j];
    }
    __syncthreads();

    // 4-way merge per row
    if (t < RT) {
        int head[4] = {0, 0, 0, 0};
        int lb = t * 4 * KNN;
        int obase = (b * Nn + n0 + t) * KNN;
        for (int kk = 0; kk < KNN; ++kk) {
            float bv = -INFINITY; int bi = 0x7fffffff; int bs = 0;
#pragma unroll
            for (int s = 0; s < 4; ++s) {
                int h = head[s];
                if (h < KNN) {
                    float v  = s_mv[lb + s * KNN + h];
                    int   im = s_mi[lb + s * KNN + h];
                    if (v > bv || (v == bv && im < bi)) { bv = v; bi = im; bs = s; }
                }
            }
            g_idx[obase + kk] = bi;
            head[bs]++;
        }
    }
}

// ---------------- K3: projections ----------------
__global__ void proj_kernel(const float* __restrict__ x, const float* __restrict__ W) {
    __shared__ float s_w1[Cn][On];
    __shared__ float s_wd[Cn][On];
    __shared__ float s_x[Cn][32];

    int t = threadIdx.x;
    for (int i = t; i < On * Cn; i += 256) {
        int o = i / Cn, c = i % Cn;
        float w1 = W[o * (2 * Cn) + c];
        float w2 = W[o * (2 * Cn) + Cn + c];
        s_w1[c][o] = w1;
        s_wd[c][o] = w2 - w1;
    }
    int b  = blockIdx.x / (Nn / 32);
    int n0 = (blockIdx.x % (Nn / 32)) * 32;
    for (int i = t; i < Cn * 32; i += 256) {
        int c = i / 32, p = i % 32;
        s_x[c][p] = x[b * Cn * Nn + c * Nn + n0 + p];
    }
    __syncthreads();

    int warp = t >> 5, lane = t & 31;
    int p0 = warp * 4;
    float au0[4] = {0,0,0,0}, au1[4] = {0,0,0,0};
    float av0[4] = {0,0,0,0}, av1[4] = {0,0,0,0};

#pragma unroll 8
    for (int c = 0; c < Cn; ++c) {
        float w1l = s_w1[c][lane], w1h = s_w1[c][lane + 32];
        float wdl = s_wd[c][lane], wdh = s_wd[c][lane + 32];
#pragma unroll
        for (int pp = 0; pp < 4; ++pp) {
            float xv = s_x[c][p0 + pp];
            au0[pp] = fmaf(xv, w1l, au0[pp]);
            au1[pp] = fmaf(xv, w1h, au1[pp]);
            av0[pp] = fmaf(xv, wdl, av0[pp]);
            av1[pp] = fmaf(xv, wdh, av1[pp]);
        }
    }
#pragma unroll
    for (int pp = 0; pp < 4; ++pp) {
        int pt = b * Nn + n0 + p0 + pp;
        g_u[pt * On + lane]      = au0[pp];
        g_u[pt * On + 32 + lane] = au1[pp];
        g_v[pt * On + lane]      = av0[pp];
        g_v[pt * On + 32 + lane] = av1[pp];
    }
}

// ---------------- K0: zero stats ----------------
__global__ void zero_kernel() {
    int t = threadIdx.x;
    if (t < On) { g_sum[t] = 0.f; g_sumsq[t] = 0.f; }
}

// ---------------- K4: gather, max/min over k, stats ----------------
__global__ void maxstats_kernel(const float* __restrict__ gamma) {
    __shared__ float ssum[8][On];
    __shared__ float ssq[8][On];
    int warp = threadIdx.x >> 5, lane = threadIdx.x & 31;
    int pt = blockIdx.x * 8 + warp;
    int b = pt >> 12;

    const float* vp = g_v + pt * On;
    float v0 = vp[lane], v1 = vp[lane + 32];
    float mx0 = -INFINITY, mx1 = -INFINITY, mn0 = INFINITY, mn1 = INFINITY;
    float s0 = 0.f, s1 = 0.f, q0 = 0.f, q1 = 0.f;
    const int* ip = g_idx + pt * KNN;

#pragma unroll
    for (int k = 0; k < KNN; ++k) {
        int m = ip[k];
        const float* up = g_u + ((b << 12) + m) * On;
        float y0 = up[lane] + v0;
        float y1 = up[lane + 32] + v1;
        mx0 = fmaxf(mx0, y0); mn0 = fminf(mn0, y0);
        mx1 = fmaxf(mx1, y1); mn1 = fminf(mn1, y1);
        s0 += y0; q0 = fmaf(y0, y0, q0);
        s1 += y1; q1 = fmaf(y1, y1, q1);
    }
    float g0 = gamma[lane], g1 = gamma[lane + 32];
    g_sel[pt * On + lane]      = (g0 >= 0.f) ? mx0 : mn0;
    g_sel[pt * On + 32 + lane] = (g1 >= 0.f) ? mx1 : mn1;

    ssum[warp][lane] = s0; ssum[warp][lane + 32] = s1;
    ssq[warp][lane]  = q0; ssq[warp][lane + 32]  = q1;
    __syncthreads();
    if (threadIdx.x < On) {
        float ts = 0.f, tq = 0.f;
#pragma unroll
        for (int w = 0; w < 8; ++w) { ts += ssum[w][threadIdx.x]; tq += ssq[w][threadIdx.x]; }
        atomicAdd(&g_sum[threadIdx.x], ts);
        atomicAdd(&g_sumsq[threadIdx.x], tq);
    }
}

// ---------------- K6: BN coefficients ----------------
__global__ void bnfinal_kernel(const float* __restrict__ gamma, const float* __restrict__ beta) {
    int o = threadIdx.x;
    if (o < On) {
        const float M = (float)(Bn * Nn * KNN);
        float mean = g_sum[o] / M;
        float var  = g_sumsq[o] / M - mean * mean;
        var = fmaxf(var, 0.f);
        float a = gamma[o] * rsqrtf(var + EPSC);
        g_cA[o] = a;
        g_cB[o] = beta[o] - mean * a;
    }
}

// ---------------- K7: finalize + transpose ----------------
__global__ void finalize_kernel(float* __restrict__ out) {
    __shared__ float tile[32][On + 1];
    __shared__ float sA[On], sB[On];
    int t = threadIdx.x;
    int b  = blockIdx.x / (Nn / 32);
    int n0 = (blockIdx.x % (Nn / 32)) * 32;
    if (t < On) { sA[t] = g_cA[t]; sB[t] = g_cB[t]; }
    for (int i = t; i < 32 * On; i += 256) {
        int nl = i / On, o = i % On;
        tile[nl][o] = g_sel[(b * Nn + n0) * On + i];
    }
    __syncthreads();
    for (int i = t; i < 32 * On; i += 256) {
        int o = i / 32, nl = i % 32;
        float y = tile[nl][o];
        float val = fmaf(sA[o], y, sB[o]);
        out[b * On * Nn + o * Nn + n0 + nl] = (val >= 0.f) ? val : SLOPE * val;
    }
}

// ---------------- launch ----------------
// knn kept at launch position 4 so the harness ncu capture (-s 5 -c 1) hits it.
extern "C" void kernel_launch(void* const* d_in, const int* in_sizes, int n_in,
                              void* d_out, int out_size) {
    const float* x     = (const float*)d_in[0];
    const float* W     = (const float*)d_in[1];
    const float* gamma = (const float*)d_in[2];
    const float* beta  = (const float*)d_in[3];
    float* out = (float*)d_out;

    cudaFuncSetAttribute(knn_kernel, cudaFuncAttributeMaxDynamicSharedMemorySize, SMEM_KNN);

    xx_kernel<<<(Bn * Nn) / 256, 256>>>(x);
    proj_kernel<<<Bn * (Nn / 32), 256>>>(x, W);
    zero_kernel<<<1, 64>>>();
    knn_kernel<<<Bn * (Nn / RT), 256, SMEM_KNN>>>(x);
    maxstats_kernel<<<(Bn * Nn) / 8, 256>>>(gamma);
    bnfinal_kernel<<<1, 64>>>(gamma, beta);
    finalize_kernel<<<Bn * (Nn / 32), 256>>>(out);
}

// round 9
// speedup vs baseline: 1.0008x; 1.0008x over previous
#include <cuda_runtime.h>
#include <math.h>

#define Bn   8
#define Cn   64
#define Nn   4096
#define On   64
#define KNN  20
#define SLOPE 0.2f
#define EPSC  1e-5f

// packed fp32x2 FMA (sm_103a) — only reachable via PTX
#define FMA_F32X2(d, a, b) \
    asm("fma.rn.f32x2 %0, %1, %2, %0;" : "+l"(d) : "l"(a), "l"(b))
#define PACK_F32X2(out, lo, hi) \
    asm("mov.b64 %0, {%1, %2};" : "=l"(out) : "f"(lo), "f"(hi))

// ---------------- device scratch ----------------
__device__ float g_xx[Bn * Nn];
__device__ int   g_idx[Bn * Nn * KNN];
__device__ float g_u[Bn * Nn * On];
__device__ float g_v[Bn * Nn * On];
__device__ float g_sel[Bn * Nn * On];
__device__ float g_sum[On];
__device__ float g_sumsq[On];
__device__ float g_cA[On];
__device__ float g_cB[On];

// ---------------- K1: squared norms ----------------
__global__ void xx_kernel(const float* __restrict__ x) {
    int i = blockIdx.x * 256 + threadIdx.x;
    int b = i >> 12;
    int n = i & (Nn - 1);
    const float* xp = x + b * Cn * Nn + n;
    float s = 0.f;
#pragma unroll
    for (int c = 0; c < Cn; ++c) {
        float v = xp[c * Nn];
        s = fmaf(v, v, s);
    }
    g_xx[i] = s;
}

// ---------------- K2: distance GEMM + top-K (R5 config + float4 loader) ------
// 256 threads = 16 rg x 16 cg; thread computes 4 rows x 8 cols (two LDS.128
// groups colA/colB, conflict-free). 2 CTAs/SM, 128 regs (NO reg-count cap:
// R6 proved forcing 3 CTAs spills vals/acc to local = 3x regression).
#define RT 64
#define MTile 128
#define SKEW 36

#define OFF_XC   0                    // 64*64 f   = 16384 B
#define OFF_XXM  16384                // 128 f     = 512 B
#define OFF_XM   16896                // 64*128 f  = 32768 B
#define OFF_SC   49664                // 256*36 f  = 36864 B
#define OFF_MINV 86528                // 256 f     = 1024 B
#define OFF_MV   0                    // 256*20 f (post-loop reuse)
#define OFF_MI   20480                // 256*20 i (post-loop reuse)
#define SMEM_KNN 87552

__global__ void __launch_bounds__(256, 2) knn_kernel(const float* __restrict__ x) {
    extern __shared__ char smraw[];
    float* s_xc   = (float*)(smraw + OFF_XC);
    float* s_xxm  = (float*)(smraw + OFF_XXM);
    float* s_xm   = (float*)(smraw + OFF_XM);
    float* s_sc   = (float*)(smraw + OFF_SC);
    float* s_minv = (float*)(smraw + OFF_MINV);
    float* s_mv   = (float*)(smraw + OFF_MV);
    int*   s_mi   = (int*)  (smraw + OFF_MI);

    int t  = threadIdx.x;
    int b  = blockIdx.x >> 6;
    int n0 = (blockIdx.x & 63) * RT;
    const float*  xb  = x + b * Cn * Nn;
    const float4* xb4 = (const float4*)xb;        // row stride Nn/4 = 1024

    // center tile [c][row], vectorized: 64*64/4 = 1024 float4, 4 per thread
    {
        float4* s_xc4 = (float4*)s_xc;
#pragma unroll
        for (int i = t; i < Cn * RT / 4; i += 256) {
            int c = i >> 4, r4 = i & 15;          // 16 float4 per row of 64
            s_xc4[c * 16 + r4] = xb4[c * (Nn / 4) + (n0 >> 2) + r4];
        }
    }
    s_minv[t] = -INFINITY;

    int cg = t & 15, rg = t >> 4;
    int row0 = rg * 4;
    int colA = cg * 4;            // cols colA..colA+3
    int colB = 64 + cg * 4;       // cols colB..colB+3
    int qA = cg >> 3;             // quarter of colA (0 or 1)
    int slot = (cg & 7) * 4;

    float vals[KNN];
    int   idxs[KNN];
#pragma unroll
    for (int j = 0; j < KNN; ++j) { vals[j] = -INFINITY; idxs[j] = 0x7fffffff; }

    int sbase = t * SKEW;          // scan-owner base
    int mcol0 = (t & 3) * 32;      // scan-owner column quarter
    int thrb  = t & ~3;            // row's 4 owners

    float4* s_xm4 = (float4*)s_xm;
    const float4* gxx4 = (const float4*)(g_xx + b * Nn);

    for (int m0 = 0; m0 < Nn; m0 += MTile) {
        // candidate tile: 64*128/4 = 2048 float4, 8 per thread (LDG.128/STS.128)
#pragma unroll
        for (int i = t; i < Cn * MTile / 4; i += 256) {
            int c = i >> 5, m4 = i & 31;          // 32 float4 per row of 128
            s_xm4[c * 32 + m4] = xb4[c * (Nn / 4) + (m0 >> 2) + m4];
        }
        if (t < MTile / 4) ((float4*)s_xxm)[t] = gxx4[(m0 >> 2) + t];
        __syncthreads();

        unsigned long long acc2[4][4];
#pragma unroll
        for (int rr = 0; rr < 4; ++rr)
#pragma unroll
            for (int jp = 0; jp < 4; ++jp) acc2[rr][jp] = 0ULL;

#pragma unroll 8
        for (int c = 0; c < Cn; ++c) {
            float4 xr = *(const float4*)(s_xc + c * RT + row0);
            ulonglong2 A0 = *(const ulonglong2*)(s_xm + c * MTile + colA);
            ulonglong2 A1 = *(const ulonglong2*)(s_xm + c * MTile + colB);
            unsigned long long av2[4] = {A0.x, A0.y, A1.x, A1.y};
            unsigned long long rs[4];
            PACK_F32X2(rs[0], xr.x, xr.x);
            PACK_F32X2(rs[1], xr.y, xr.y);
            PACK_F32X2(rs[2], xr.z, xr.z);
            PACK_F32X2(rs[3], xr.w, xr.w);
#pragma unroll
            for (int rr = 0; rr < 4; ++rr)
#pragma unroll
                for (int jp = 0; jp < 4; ++jp)
                    FMA_F32X2(acc2[rr][jp], rs[rr], av2[jp]);
        }

        // stage scores owner-major: owner = row*4 + quarter, slot = col%32
        float4 xxA = *(const float4*)(s_xxm + colA);
        float4 xxB = *(const float4*)(s_xxm + colB);
#pragma unroll
        for (int rr = 0; rr < 4; ++rr) {
            float2 pa0 = *reinterpret_cast<float2*>(&acc2[rr][0]);
            float2 pa1 = *reinterpret_cast<float2*>(&acc2[rr][1]);
            float2 pb0 = *reinterpret_cast<float2*>(&acc2[rr][2]);
            float2 pb1 = *reinterpret_cast<float2*>(&acc2[rr][3]);
            float4 scA = make_float4(fmaf(2.f, pa0.x, -xxA.x),
                                     fmaf(2.f, pa0.y, -xxA.y),
                                     fmaf(2.f, pa1.x, -xxA.z),
                                     fmaf(2.f, pa1.y, -xxA.w));
            float4 scB = make_float4(fmaf(2.f, pb0.x, -xxB.x),
                                     fmaf(2.f, pb0.y, -xxB.y),
                                     fmaf(2.f, pb1.x, -xxB.z),
                                     fmaf(2.f, pb1.y, -xxB.w));
            int owA = (row0 + rr) * 4 + qA;
            *(float4*)(s_sc + owA * SKEW + slot)       = scA;
            *(float4*)(s_sc + (owA + 2) * SKEW + slot) = scB;
        }
        __syncthreads();

        // shared row threshold (benign-stale read)
        float thr = fmaxf(fmaxf(s_minv[thrb], s_minv[thrb + 1]),
                          fmaxf(s_minv[thrb + 2], s_minv[thrb + 3]));

        // prescan: load 32 scores, tile max
        float4 sc4[8];
#pragma unroll
        for (int q = 0; q < 8; ++q) sc4[q] = *(const float4*)(s_sc + sbase + q * 4);
        float tmax = -INFINITY;
#pragma unroll
        for (int q = 0; q < 8; ++q) {
            tmax = fmaxf(tmax, fmaxf(fmaxf(sc4[q].x, sc4[q].y), fmaxf(sc4[q].z, sc4[q].w)));
        }
        float thr_eff = fmaxf(thr, vals[KNN - 1]);

        if (tmax > thr_eff) {
            int mbase = m0 + mcol0;
            const float* scr = (const float*)sc4;
#pragma unroll
            for (int j = 0; j < 32; ++j) {
                float sc = scr[j];
                if (sc > vals[KNN - 1] && sc > thr) {
                    vals[KNN - 1] = sc; idxs[KNN - 1] = mbase + j;
#pragma unroll
                    for (int qq = KNN - 1; qq > 0; --qq) {
                        bool sw = vals[qq] > vals[qq - 1];
                        float tv = sw ? vals[qq - 1] : vals[qq];
                        float tu = sw ? vals[qq]     : vals[qq - 1];
                        int   ti = sw ? idxs[qq - 1] : idxs[qq];
                        int   tj = sw ? idxs[qq]     : idxs[qq - 1];
                        vals[qq] = tv; vals[qq - 1] = tu;
                        idxs[qq] = ti; idxs[qq - 1] = tj;
                    }
                }
            }
            s_minv[t] = vals[KNN - 1];
        }
        __syncthreads();
    }

    // dump per-thread sorted lists
#pragma unroll
    for (int j = 0; j < KNN; ++j) {
        s_mv[t * KNN + j] = vals[j];
        s_mi[t * KNN + j] = idxs[j];
    }
    __syncthreads();

    // 4-way merge per row
    if (t < RT) {
        int head[4] = {0, 0, 0, 0};
        int lb = t * 4 * KNN;
        int obase = (b * Nn + n0 + t) * KNN;
        for (int kk = 0; kk < KNN; ++kk) {
            float bv = -INFINITY; int bi = 0x7fffffff; int bs = 0;
#pragma unroll
            for (int s = 0; s < 4; ++s) {
                int h = head[s];
                if (h < KNN) {
                    float v  = s_mv[lb + s * KNN + h];
                    int   im = s_mi[lb + s * KNN + h];
                    if (v > bv || (v == bv && im < bi)) { bv = v; bi = im; bs = s; }
                }
            }
            g_idx[obase + kk] = bi;
            head[bs]++;
        }
    }
}

// ---------------- K3: projections ----------------
__global__ void proj_kernel(const float* __restrict__ x, const float* __restrict__ W) {
    __shared__ float s_w1[Cn][On];
    __shared__ float s_wd[Cn][On];
    __shared__ float s_x[Cn][32];

    int t = threadIdx.x;
    for (int i = t; i < On * Cn; i += 256) {
        int o = i / Cn, c = i % Cn;
        float w1 = W[o * (2 * Cn) + c];
        float w2 = W[o * (2 * Cn) + Cn + c];
        s_w1[c][o] = w1;
        s_wd[c][o] = w2 - w1;
    }
    int b  = blockIdx.x / (Nn / 32);
    int n0 = (blockIdx.x % (Nn / 32)) * 32;
    for (int i = t; i < Cn * 32; i += 256) {
        int c = i / 32, p = i % 32;
        s_x[c][p] = x[b * Cn * Nn + c * Nn + n0 + p];
    }
    __syncthreads();

    int warp = t >> 5, lane = t & 31;
    int p0 = warp * 4;
    float au0[4] = {0,0,0,0}, au1[4] = {0,0,0,0};
    float av0[4] = {0,0,0,0}, av1[4] = {0,0,0,0};

#pragma unroll 8
    for (int c = 0; c < Cn; ++c) {
        float w1l = s_w1[c][lane], w1h = s_w1[c][lane + 32];
        float wdl = s_wd[c][lane], wdh = s_wd[c][lane + 32];
#pragma unroll
        for (int pp = 0; pp < 4; ++pp) {
            float xv = s_x[c][p0 + pp];
            au0[pp] = fmaf(xv, w1l, au0[pp]);
            au1[pp] = fmaf(xv, w1h, au1[pp]);
            av0[pp] = fmaf(xv, wdl, av0[pp]);
            av1[pp] = fmaf(xv, wdh, av1[pp]);
        }
    }
#pragma unroll
    for (int pp = 0; pp < 4; ++pp) {
        int pt = b * Nn + n0 + p0 + pp;
        g_u[pt * On + lane]      = au0[pp];
        g_u[pt * On + 32 + lane] = au1[pp];
        g_v[pt * On + lane]      = av0[pp];
        g_v[pt * On + 32 + lane] = av1[pp];
    }
}

// ---------------- K0: zero stats ----------------
__global__ void zero_kernel() {
    int t = threadIdx.x;
    if (t < On) { g_sum[t] = 0.f; g_sumsq[t] = 0.f; }
}

// ---------------- K4: gather, max/min over k, stats ----------------
__global__ void maxstats_kernel(const float* __restrict__ gamma) {
    __shared__ float ssum[8][On];
    __shared__ float ssq[8][On];
    int warp = threadIdx.x >> 5, lane = threadIdx.x & 31;
    int pt = blockIdx.x * 8 + warp;
    int b = pt >> 12;

    const float* vp = g_v + pt * On;
    float v0 = vp[lane], v1 = vp[lane + 32];
    float mx0 = -INFINITY, mx1 = -INFINITY, mn0 = INFINITY, mn1 = INFINITY;
    float s0 = 0.f, s1 = 0.f, q0 = 0.f, q1 = 0.f;
    const int* ip = g_idx + pt * KNN;

#pragma unroll
    for (int k = 0; k < KNN; ++k) {
        int m = ip[k];
        const float* up = g_u + ((b << 12) + m) * On;
        float y0 = up[lane] + v0;
        float y1 = up[lane + 32] + v1;
        mx0 = fmaxf(mx0, y0); mn0 = fminf(mn0, y0);
        mx1 = fmaxf(mx1, y1); mn1 = fminf(mn1, y1);
        s0 += y0; q0 = fmaf(y0, y0, q0);
        s1 += y1; q1 = fmaf(y1, y1, q1);
    }
    float g0 = gamma[lane], g1 = gamma[lane + 32];
    g_sel[pt * On + lane]      = (g0 >= 0.f) ? mx0 : mn0;
    g_sel[pt * On + 32 + lane] = (g1 >= 0.f) ? mx1 : mn1;

    ssum[warp][lane] = s0; ssum[warp][lane + 32] = s1;
    ssq[warp][lane]  = q0; ssq[warp][lane + 32]  = q1;
    __syncthreads();
    if (threadIdx.x < On) {
        float ts = 0.f, tq = 0.f;
#pragma unroll
        for (int w = 0; w < 8; ++w) { ts += ssum[w][threadIdx.x]; tq += ssq[w][threadIdx.x]; }
        atomicAdd(&g_sum[threadIdx.x], ts);
        atomicAdd(&g_sumsq[threadIdx.x], tq);
    }
}

// ---------------- K6: BN coefficients ----------------
__global__ void bnfinal_kernel(const float* __restrict__ gamma, const float* __restrict__ beta) {
    int o = threadIdx.x;
    if (o < On) {
        const float M = (float)(Bn * Nn * KNN);
        float mean = g_sum[o] / M;
        float var  = g_sumsq[o] / M - mean * mean;
        var = fmaxf(var, 0.f);
        float a = gamma[o] * rsqrtf(var + EPSC);
        g_cA[o] = a;
        g_cB[o] = beta[o] - mean * a;
    }
}

// ---------------- K7: finalize + transpose ----------------
__global__ void finalize_kernel(float* __restrict__ out) {
    __shared__ float tile[32][On + 1];
    __shared__ float sA[On], sB[On];
    int t = threadIdx.x;
    int b  = blockIdx.x / (Nn / 32);
    int n0 = (blockIdx.x % (Nn / 32)) * 32;
    if (t < On) { sA[t] = g_cA[t]; sB[t] = g_cB[t]; }
    for (int i = t; i < 32 * On; i += 256) {
        int nl = i / On, o = i % On;
        tile[nl][o] = g_sel[(b * Nn + n0) * On + i];
    }
    __syncthreads();
    for (int i = t; i < 32 * On; i += 256) {
        int o = i / 32, nl = i % 32;
        float y = tile[nl][o];
        float val = fmaf(sA[o], y, sB[o]);
        out[b * On * Nn + o * Nn + n0 + nl] = (val >= 0.f) ? val : SLOPE * val;
    }
}

// ---------------- launch ----------------
// knn kept at launch position 4 so the harness ncu capture (-s 5 -c 1) hits it.
extern "C" void kernel_launch(void* const* d_in, const int* in_sizes, int n_in,
                              void* d_out, int out_size) {
    const float* x     = (const float*)d_in[0];
    const float* W     = (const float*)d_in[1];
    const float* gamma = (const float*)d_in[2];
    const float* beta  = (const float*)d_in[3];
    float* out = (float*)d_out;

    cudaFuncSetAttribute(knn_kernel, cudaFuncAttributeMaxDynamicSharedMemorySize, SMEM_KNN);

    xx_kernel<<<(Bn * Nn) / 256, 256>>>(x);
    proj_kernel<<<Bn * (Nn / 32), 256>>>(x, W);
    zero_kernel<<<1, 64>>>();
    knn_kernel<<<Bn * (Nn / RT), 256, SMEM_KNN>>>(x);
    maxstats_kernel<<<(Bn * Nn) / 8, 256>>>(gamma);
    bnfinal_kernel<<<1, 64>>>(gamma, beta);
    finalize_kernel<<<Bn * (Nn / 32), 256>>>(out);
}

// round 10
// speedup vs baseline: 1.0026x; 1.0018x over previous
#include <cuda_runtime.h>
#include <math.h>

#define Bn   8
#define Cn   64
#define Nn   4096
#define On   64
#define KNN  20
#define SLOPE 0.2f
#define EPSC  1e-5f

// packed fp32x2 FMA (sm_103a) — only reachable via PTX
#define FMA_F32X2(d, a, b) \
    asm("fma.rn.f32x2 %0, %1, %2, %0;" : "+l"(d) : "l"(a), "l"(b))
#define PACK_F32X2(out, lo, hi) \
    asm("mov.b64 %0, {%1, %2};" : "=l"(out) : "f"(lo), "f"(hi))

// ---------------- device scratch ----------------
__device__ float g_xx[Bn * Nn];
__device__ int   g_idx[Bn * Nn * KNN];
__device__ float g_u[Bn * Nn * On];
__device__ float g_v[Bn * Nn * On];
__device__ float g_sel[Bn * Nn * On];
__device__ float g_sum[On];
__device__ float g_sumsq[On];
__device__ float g_cA[On];
__device__ float g_cB[On];

// ---------------- K1: squared norms ----------------
__global__ void xx_kernel(const float* __restrict__ x) {
    int i = blockIdx.x * 256 + threadIdx.x;
    int b = i >> 12;
    int n = i & (Nn - 1);
    const float* xp = x + b * Cn * Nn + n;
    float s = 0.f;
#pragma unroll
    for (int c = 0; c < Cn; ++c) {
        float v = xp[c * Nn];
        s = fmaf(v, v, s);
    }
    g_xx[i] = s;
}

// ---------------- K2: distance GEMM + top-K (R5 config + float4 loader) ------
// 256 threads = 16 rg x 16 cg; thread computes 4 rows x 8 cols (two LDS.128
// groups colA/colB, conflict-free). 2 CTAs/SM, 128 regs (NO reg-count cap:
// R6 proved forcing 3 CTAs spills vals/acc to local = 3x regression).
#define RT 64
#define MTile 128
#define SKEW 36

#define OFF_XC   0                    // 64*64 f   = 16384 B
#define OFF_XXM  16384                // 128 f     = 512 B
#define OFF_XM   16896                // 64*128 f  = 32768 B
#define OFF_SC   49664                // 256*36 f  = 36864 B
#define OFF_MINV 86528                // 256 f     = 1024 B
#define OFF_MV   0                    // 256*20 f (post-loop reuse)
#define OFF_MI   20480                // 256*20 i (post-loop reuse)
#define SMEM_KNN 87552

__global__ void __launch_bounds__(256, 2) knn_kernel(const float* __restrict__ x) {
    extern __shared__ char smraw[];
    float* s_xc   = (float*)(smraw + OFF_XC);
    float* s_xxm  = (float*)(smraw + OFF_XXM);
    float* s_xm   = (float*)(smraw + OFF_XM);
    float* s_sc   = (float*)(smraw + OFF_SC);
    float* s_minv = (float*)(smraw + OFF_MINV);
    float* s_mv   = (float*)(smraw + OFF_MV);
    int*   s_mi   = (int*)  (smraw + OFF_MI);

    int t  = threadIdx.x;
    int b  = blockIdx.x >> 6;
    int n0 = (blockIdx.x & 63) * RT;
    const float*  xb  = x + b * Cn * Nn;
    const float4* xb4 = (const float4*)xb;        // row stride Nn/4 = 1024

    // center tile [c][row], vectorized: 64*64/4 = 1024 float4, 4 per thread
    {
        float4* s_xc4 = (float4*)s_xc;
#pragma unroll
        for (int i = t; i < Cn * RT / 4; i += 256) {
            int c = i >> 4, r4 = i & 15;          // 16 float4 per row of 64
            s_xc4[c * 16 + r4] = xb4[c * (Nn / 4) + (n0 >> 2) + r4];
        }
    }
    s_minv[t] = -INFINITY;

    int cg = t & 15, rg = t >> 4;
    int row0 = rg * 4;
    int colA = cg * 4;            // cols colA..colA+3
    int colB = 64 + cg * 4;       // cols colB..colB+3
    int qA = cg >> 3;             // quarter of colA (0 or 1)
    int slot = (cg & 7) * 4;

    float vals[KNN];
    int   idxs[KNN];
#pragma unroll
    for (int j = 0; j < KNN; ++j) { vals[j] = -INFINITY; idxs[j] = 0x7fffffff; }

    int sbase = t * SKEW;          // scan-owner base
    int mcol0 = (t & 3) * 32;      // scan-owner column quarter
    int thrb  = t & ~3;            // row's 4 owners

    float4* s_xm4 = (float4*)s_xm;
    const float4* gxx4 = (const float4*)(g_xx + b * Nn);

    for (int m0 = 0; m0 < Nn; m0 += MTile) {
        // candidate tile: 64*128/4 = 2048 float4, 8 per thread (LDG.128/STS.128)
#pragma unroll
        for (int i = t; i < Cn * MTile / 4; i += 256) {
            int c = i >> 5, m4 = i & 31;          // 32 float4 per row of 128
            s_xm4[c * 32 + m4] = xb4[c * (Nn / 4) + (m0 >> 2) + m4];
        }
        if (t < MTile / 4) ((float4*)s_xxm)[t] = gxx4[(m0 >> 2) + t];
        __syncthreads();

        unsigned long long acc2[4][4];
#pragma unroll
        for (int rr = 0; rr < 4; ++rr)
#pragma unroll
            for (int jp = 0; jp < 4; ++jp) acc2[rr][jp] = 0ULL;

#pragma unroll 8
        for (int c = 0; c < Cn; ++c) {
            float4 xr = *(const float4*)(s_xc + c * RT + row0);
            ulonglong2 A0 = *(const ulonglong2*)(s_xm + c * MTile + colA);
            ulonglong2 A1 = *(const ulonglong2*)(s_xm + c * MTile + colB);
            unsigned long long av2[4] = {A0.x, A0.y, A1.x, A1.y};
            unsigned long long rs[4];
            PACK_F32X2(rs[0], xr.x, xr.x);
            PACK_F32X2(rs[1], xr.y, xr.y);
            PACK_F32X2(rs[2], xr.z, xr.z);
            PACK_F32X2(rs[3], xr.w, xr.w);
#pragma unroll
            for (int rr = 0; rr < 4; ++rr)
#pragma unroll
                for (int jp = 0; jp < 4; ++jp)
                    FMA_F32X2(acc2[rr][jp], rs[rr], av2[jp]);
        }

        // stage scores owner-major: owner = row*4 + quarter, slot = col%32
        float4 xxA = *(const float4*)(s_xxm + colA);
        float4 xxB = *(const float4*)(s_xxm + colB);
#pragma unroll
        for (int rr = 0; rr < 4; ++rr) {
            float2 pa0 = *reinterpret_cast<float2*>(&acc2[rr][0]);
            float2 pa1 = *reinterpret_cast<float2*>(&acc2[rr][1]);
            float2 pb0 = *reinterpret_cast<float2*>(&acc2[rr][2]);
            float2 pb1 = *reinterpret_cast<float2*>(&acc2[rr][3]);
            float4 scA = make_float4(fmaf(2.f, pa0.x, -xxA.x),
                                     fmaf(2.f, pa0.y, -xxA.y),
                                     fmaf(2.f, pa1.x, -xxA.z),
                                     fmaf(2.f, pa1.y, -xxA.w));
            float4 scB = make_float4(fmaf(2.f, pb0.x, -xxB.x),
                                     fmaf(2.f, pb0.y, -xxB.y),
                                     fmaf(2.f, pb1.x, -xxB.z),
                                     fmaf(2.f, pb1.y, -xxB.w));
            int owA = (row0 + rr) * 4 + qA;
            *(float4*)(s_sc + owA * SKEW + slot)       = scA;
            *(float4*)(s_sc + (owA + 2) * SKEW + slot) = scB;
        }
        __syncthreads();

        // shared row threshold (benign-stale read)
        float thr = fmaxf(fmaxf(s_minv[thrb], s_minv[thrb + 1]),
                          fmaxf(s_minv[thrb + 2], s_minv[thrb + 3]));

        // prescan: load 32 scores, tile max
        float4 sc4[8];
#pragma unroll
        for (int q = 0; q < 8; ++q) sc4[q] = *(const float4*)(s_sc + sbase + q * 4);
        float tmax = -INFINITY;
#pragma unroll
        for (int q = 0; q < 8; ++q) {
            tmax = fmaxf(tmax, fmaxf(fmaxf(sc4[q].x, sc4[q].y), fmaxf(sc4[q].z, sc4[q].w)));
        }
        float thr_eff = fmaxf(thr, vals[KNN - 1]);

        if (tmax > thr_eff) {
            int mbase = m0 + mcol0;
            const float* scr = (const float*)sc4;
#pragma unroll
            for (int j = 0; j < 32; ++j) {
                float sc = scr[j];
                if (sc > vals[KNN - 1] && sc > thr) {
                    vals[KNN - 1] = sc; idxs[KNN - 1] = mbase + j;
#pragma unroll
                    for (int qq = KNN - 1; qq > 0; --qq) {
                        bool sw = vals[qq] > vals[qq - 1];
                        float tv = sw ? vals[qq - 1] : vals[qq];
                        float tu = sw ? vals[qq]     : vals[qq - 1];
                        int   ti = sw ? idxs[qq - 1] : idxs[qq];
                        int   tj = sw ? idxs[qq]     : idxs[qq - 1];
                        vals[qq] = tv; vals[qq - 1] = tu;
                        idxs[qq] = ti; idxs[qq - 1] = tj;
                    }
                }
            }
            s_minv[t] = vals[KNN - 1];
        }
        __syncthreads();
    }

    // dump per-thread sorted lists
#pragma unroll
    for (int j = 0; j < KNN; ++j) {
        s_mv[t * KNN + j] = vals[j];
        s_mi[t * KNN + j] = idxs[j];
    }
    __syncthreads();

    // 4-way merge per row
    if (t < RT) {
        int head[4] = {0, 0, 0, 0};
        int lb = t * 4 * KNN;
        int obase = (b * Nn + n0 + t) * KNN;
        for (int kk = 0; kk < KNN; ++kk) {
            float bv = -INFINITY; int bi = 0x7fffffff; int bs = 0;
#pragma unroll
            for (int s = 0; s < 4; ++s) {
                int h = head[s];
                if (h < KNN) {
                    float v  = s_mv[lb + s * KNN + h];
                    int   im = s_mi[lb + s * KNN + h];
                    if (v > bv || (v == bv && im < bi)) { bv = v; bi = im; bs = s; }
                }
            }
            g_idx[obase + kk] = bi;
            head[bs]++;
        }
    }
}

// ---------------- K3: projections ----------------
__global__ void proj_kernel(const float* __restrict__ x, const float* __restrict__ W) {
    __shared__ float s_w1[Cn][On];
    __shared__ float s_wd[Cn][On];
    __shared__ float s_x[Cn][32];

    int t = threadIdx.x;
    for (int i = t; i < On * Cn; i += 256) {
        int o = i / Cn, c = i % Cn;
        float w1 = W[o * (2 * Cn) + c];
        float w2 = W[o * (2 * Cn) + Cn + c];
        s_w1[c][o] = w1;
        s_wd[c][o] = w2 - w1;
    }
    int b  = blockIdx.x / (Nn / 32);
    int n0 = (blockIdx.x % (Nn / 32)) * 32;
    for (int i = t; i < Cn * 32; i += 256) {
        int c = i / 32, p = i % 32;
        s_x[c][p] = x[b * Cn * Nn + c * Nn + n0 + p];
    }
    __syncthreads();

    int warp = t >> 5, lane = t & 31;
    int p0 = warp * 4;
    float au0[4] = {0,0,0,0}, au1[4] = {0,0,0,0};
    float av0[4] = {0,0,0,0}, av1[4] = {0,0,0,0};

#pragma unroll 8
    for (int c = 0; c < Cn; ++c) {
        float w1l = s_w1[c][lane], w1h = s_w1[c][lane + 32];
        float wdl = s_wd[c][lane], wdh = s_wd[c][lane + 32];
#pragma unroll
        for (int pp = 0; pp < 4; ++pp) {
            float xv = s_x[c][p0 + pp];
            au0[pp] = fmaf(xv, w1l, au0[pp]);
            au1[pp] = fmaf(xv, w1h, au1[pp]);
            av0[pp] = fmaf(xv, wdl, av0[pp]);
            av1[pp] = fmaf(xv, wdh, av1[pp]);
        }
    }
#pragma unroll
    for (int pp = 0; pp < 4; ++pp) {
        int pt = b * Nn + n0 + p0 + pp;
        g_u[pt * On + lane]      = au0[pp];
        g_u[pt * On + 32 + lane] = au1[pp];
        g_v[pt * On + lane]      = av0[pp];
        g_v[pt * On + 32 + lane] = av1[pp];
    }
}

// ---------------- K0: zero stats ----------------
__global__ void zero_kernel() {
    int t = threadIdx.x;
    if (t < On) { g_sum[t] = 0.f; g_sumsq[t] = 0.f; }
}

// ---------------- K4: gather, max/min over k, stats ----------------
__global__ void maxstats_kernel(const float* __restrict__ gamma) {
    __shared__ float ssum[8][On];
    __shared__ float ssq[8][On];
    int warp = threadIdx.x >> 5, lane = threadIdx.x & 31;
    int pt = blockIdx.x * 8 + warp;
    int b = pt >> 12;

    const float* vp = g_v + pt * On;
    float v0 = vp[lane], v1 = vp[lane + 32];
    float mx0 = -INFINITY, mx1 = -INFINITY, mn0 = INFINITY, mn1 = INFINITY;
    float s0 = 0.f, s1 = 0.f, q0 = 0.f, q1 = 0.f;
    const int* ip = g_idx + pt * KNN;

#pragma unroll
    for (int k = 0; k < KNN; ++k) {
        int m = ip[k];
        const float* up = g_u + ((b << 12) + m) * On;
        float y0 = up[lane] + v0;
        float y1 = up[lane + 32] + v1;
        mx0 = fmaxf(mx0, y0); mn0 = fminf(mn0, y0);
        mx1 = fmaxf(mx1, y1); mn1 = fminf(mn1, y1);
        s0 += y0; q0 = fmaf(y0, y0, q0);
        s1 += y1; q1 = fmaf(y1, y1, q1);
    }
    float g0 = gamma[lane], g1 = gamma[lane + 32];
    g_sel[pt * On + lane]      = (g0 >= 0.f) ? mx0 : mn0;
    g_sel[pt * On + 32 + lane] = (g1 >= 0.f) ? mx1 : mn1;

    ssum[warp][lane] = s0; ssum[warp][lane + 32] = s1;
    ssq[warp][lane]  = q0; ssq[warp][lane + 32]  = q1;
    __syncthreads();
    if (threadIdx.x < On) {
        float ts = 0.f, tq = 0.f;
#pragma unroll
        for (int w = 0; w < 8; ++w) { ts += ssum[w][threadIdx.x]; tq += ssq[w][threadIdx.x]; }
        atomicAdd(&g_sum[threadIdx.x], ts);
        atomicAdd(&g_sumsq[threadIdx.x], tq);
    }
}

// ---------------- K6: BN coefficients ----------------
__global__ void bnfinal_kernel(const float* __restrict__ gamma, const float* __restrict__ beta) {
    int o = threadIdx.x;
    if (o < On) {
        const float M = (float)(Bn * Nn * KNN);
        float mean = g_sum[o] / M;
        float var  = g_sumsq[o] / M - mean * mean;
        var = fmaxf(var, 0.f);
        float a = gamma[o] * rsqrtf(var + EPSC);
        g_cA[o] = a;
        g_cB[o] = beta[o] - mean * a;
    }
}

// ---------------- K7: finalize + transpose ----------------
__global__ void finalize_kernel(float* __restrict__ out) {
    __shared__ float tile[32][On + 1];
    __shared__ float sA[On], sB[On];
    int t = threadIdx.x;
    int b  = blockIdx.x / (Nn / 32);
    int n0 = (blockIdx.x % (Nn / 32)) * 32;
    if (t < On) { sA[t] = g_cA[t]; sB[t] = g_cB[t]; }
    for (int i = t; i < 32 * On; i += 256) {
        int nl = i / On, o = i % On;
        tile[nl][o] = g_sel[(b * Nn + n0) * On + i];
    }
    __syncthreads();
    for (int i = t; i < 32 * On; i += 256) {
        int o = i / 32, nl = i % 32;
        float y = tile[nl][o];
        float val = fmaf(sA[o], y, sB[o]);
        out[b * On * Nn + o * Nn + n0 + nl] = (val >= 0.f) ? val : SLOPE * val;
    }
}

// ---------------- launch ----------------
// knn kept at launch position 4 so the harness ncu capture (-s 5 -c 1) hits it.
extern "C" void kernel_launch(void* const* d_in, const int* in_sizes, int n_in,
                              void* d_out, int out_size) {
    const float* x     = (const float*)d_in[0];
    const float* W     = (const float*)d_in[1];
    const float* gamma = (const float*)d_in[2];
    const float* beta  = (const float*)d_in[3];
    float* out = (float*)d_out;

    cudaFuncSetAttribute(knn_kernel, cudaFuncAttributeMaxDynamicSharedMemorySize, SMEM_KNN);

    xx_kernel<<<(Bn * Nn) / 256, 256>>>(x);
    proj_kernel<<<Bn * (Nn / 32), 256>>>(x, W);
    zero_kernel<<<1, 64>>>();
    knn_kernel<<<Bn * (Nn / RT), 256, SMEM_KNN>>>(x);
    maxstats_kernel<<<(Bn * Nn) / 8, 256>>>(gamma);
    bnfinal_kernel<<<1, 64>>>(gamma, beta);
    finalize_kernel<<<Bn * (Nn / 32), 256>>>(out);
}